// round 14
// baseline (speedup 1.0000x reference)
#include <cuda_runtime.h>
#include <cuda_fp16.h>
#include <cstdint>
#include <math.h>

#define NTASK 64
#define NB    4096
#define TD    512
#define HD    256
#define VD    484
#define MT    64            // batch rows per CTA
#define KC    32            // halves per staged k-chunk
#define THREADS 128

// ---- smem layout (bytes) ----
#define HSTR_B   528
#define SM_H     0
#define SM_H_SZ  (MT * HSTR_B)                  // 33792
#define STR_B    80
#define SM_STAGE SM_H_SZ
#define A_BYTES  (MT * STR_B)                   // 5120
#define STAGE_BUF (A_BYTES + 256 * STR_B)       // 25600
#define SM_PARB  (SM_STAGE + 2 * STAGE_BUF)     // 84992
#define SMEM_TOTAL (SM_PARB + 2060 * 4)         // 93232

__device__ __half g_tfeat[NB * TD];
__device__ __half g_w1[NTASK * HD * TD];
__device__ __half g_w2[NTASK * VD * HD];
__device__ unsigned int g_count;

__device__ __forceinline__ uint32_t s2u(const void* p) {
    uint32_t a;
    asm("{ .reg .u64 t; cvta.to.shared.u64 t, %1; cvt.u32.u64 %0, t; }" : "=r"(a) : "l"(p));
    return a;
}
__device__ __forceinline__ void cp16(uint32_t dst, const void* src) {
    asm volatile("cp.async.cg.shared.global [%0], [%1], 16;" :: "r"(dst), "l"(src) : "memory");
}
__device__ __forceinline__ void cpcommit() { asm volatile("cp.async.commit_group;" ::: "memory"); }
__device__ __forceinline__ void cpwait1()  { asm volatile("cp.async.wait_group 1;" ::: "memory"); }
__device__ __forceinline__ void cpwait0()  { asm volatile("cp.async.wait_group 0;" ::: "memory"); }

__device__ __forceinline__ void ldsm4(uint32_t* r, uint32_t a) {
    asm volatile("ldmatrix.sync.aligned.m8n8.x4.shared.b16 {%0,%1,%2,%3}, [%4];"
                 : "=r"(r[0]), "=r"(r[1]), "=r"(r[2]), "=r"(r[3]) : "r"(a));
}
// f16-accumulate MMA: D/C are 2 regs (f16x2 pairs)
__device__ __forceinline__ void mma16h(uint32_t* d, const uint32_t* a, uint32_t b0, uint32_t b1) {
    asm volatile(
        "mma.sync.aligned.m16n8k16.row.col.f16.f16.f16.f16 "
        "{%0,%1}, {%2,%3,%4,%5}, {%6,%7}, {%0,%1};"
        : "+r"(d[0]), "+r"(d[1])
        : "r"(a[0]), "r"(a[1]), "r"(a[2]), "r"(a[3]), "r"(b0), "r"(b1));
}
__device__ __forceinline__ void sth2(uint32_t a, __half2 v) {
    asm volatile("st.shared.b32 [%0], %1;" :: "r"(a), "r"(*(const uint32_t*)&v) : "memory");
}
__device__ __forceinline__ void stz4(uint32_t a) {
    asm volatile("st.shared.v4.b32 [%0], {%1,%1,%1,%1};" :: "r"(a), "r"(0u) : "memory");
}

// promote f16x2 accumulators into fp32 master and zero them
__device__ __forceinline__ void promote(uint32_t (&h)[4][8][2], float (&f)[4][8][4]) {
#pragma unroll
    for (int mb = 0; mb < 4; ++mb)
#pragma unroll
        for (int q = 0; q < 8; ++q) {
            const float2 fa = __half22float2(*reinterpret_cast<__half2*>(&h[mb][q][0]));
            const float2 fb = __half22float2(*reinterpret_cast<__half2*>(&h[mb][q][1]));
            f[mb][q][0] += fa.x; f[mb][q][1] += fa.y;
            f[mb][q][2] += fb.x; f[mb][q][3] += fb.y;
            h[mb][q][0] = 0u;    h[mb][q][1] = 0u;
        }
}

// ---------------- convert + zero kernel ----------------
__global__ void convert_kernel(const float* __restrict__ t_feat,
                               const float* __restrict__ W1,
                               const float* __restrict__ W2,
                               float* __restrict__ out, int out_size)
{
    const int idx = blockIdx.x * blockDim.x + threadIdx.x;
    const int stride = gridDim.x * blockDim.x;
    if (idx < 65 && idx < out_size) out[idx] = 0.0f;
    for (int i = idx; i < NB * TD / 2; i += stride) {
        const float2 v = ((const float2*)t_feat)[i];
        ((__half2*)g_tfeat)[i] = __floats2half2_rn(v.x, v.y);
    }
    for (int i = idx; i < NTASK * HD * TD / 2; i += stride) {
        const float2 v = ((const float2*)W1)[i];
        ((__half2*)g_w1)[i] = __floats2half2_rn(v.x, v.y);
    }
    for (int i = idx; i < NTASK * VD * HD / 2; i += stride) {
        const float2 v = ((const float2*)W2)[i];
        ((__half2*)g_w2)[i] = __floats2half2_rn(v.x, v.y);
    }
}

// ---------------- main fused kernel (4 warps, 64x64 warp tiles, 2 CTA/SM) ------
__global__ void __launch_bounds__(THREADS, 2)
router_h16_kernel(const float* __restrict__ b1,
                  const float* __restrict__ gamma,
                  const float* __restrict__ beta,
                  const float* __restrict__ b2,
                  const float* __restrict__ cent,
                  float* __restrict__ out, int out_size)
{
    extern __shared__ char smem[];
    const uint32_t sb = s2u(smem);
    const int tid  = threadIdx.x;
    const int lane = tid & 31;
    const int wid  = tid >> 5;          // 0..3
    const int n0w  = wid * 64;
    const int task = blockIdx.y;
    const int brow0 = blockIdx.x * MT;

    const __half* tA  = g_tfeat + (size_t)brow0 * TD;
    const __half* W1t = g_w1 + (size_t)task * HD * TD;
    const __half* W2t = g_w2 + (size_t)task * VD * HD;

    float* b1s    = (float*)(smem + SM_PARB);
    float* gms    = b1s + 256;
    float* bts    = gms + 256;
    float* b2s    = bts + 256;
    float* cts    = b2s + 512;
    float* rowSum = cts + 512;     // 64
    float* rowSq  = rowSum + 64;   // 64
    float* vcA    = rowSq + 64;    // 64
    float* vvA    = vcA + 64;      // 64
    float* red    = vvA + 64;      // 8
    int*   flag   = (int*)(red + 8);

    const int arow   = lane & 15;
    const int acol16 = (lane >> 4) * 16;
    const int brow   = (lane & 7) | ((lane >> 4) << 3);
    const int bcol16 = ((lane >> 3) & 1) * 16;
    const uint32_t aOffW = (uint32_t)(arow * STR_B + acol16);
    const uint32_t bOffW = (uint32_t)((n0w + brow) * STR_B + bcol16);
    const uint32_t hOffW = (uint32_t)(arow * HSTR_B + acol16);

    // ---- prologue: issue GEMM1 chunk 0 ----
    {
        const uint32_t ab = sb + SM_STAGE;
        const uint32_t bb = ab + A_BYTES;
#pragma unroll
        for (int i = 0; i < 2; ++i) {
            const int s = tid + 128 * i, row = s >> 2, seg = s & 3;
            cp16(ab + (uint32_t)(row * STR_B + seg * 16), tA + (size_t)row * TD + seg * 8);
        }
#pragma unroll
        for (int i = 0; i < 8; ++i) {
            const int s = tid + 128 * i, row = s >> 2, seg = s & 3;
            cp16(bb + (uint32_t)(row * STR_B + seg * 16), W1t + (size_t)row * TD + seg * 8);
        }
        cpcommit();
    }

    // ---- params + zeros ----
#pragma unroll
    for (int i = 0; i < 2; ++i) {
        const int n = tid + 128 * i;
        b1s[n] = b1[task * HD + n];
        gms[n] = gamma[task * HD + n];
        bts[n] = beta[task * HD + n];
    }
    {
        float cc = 0.f;
#pragma unroll
        for (int i = 0; i < 4; ++i) {
            const int n = tid + 128 * i;
            float bv = 0.f, cv = 0.f;
            if (n < VD) { bv = b2[task * VD + n]; cv = cent[task * VD + n]; }
            b2s[n] = bv; cts[n] = cv;
            cc = fmaf(cv, cv, cc);
        }
#pragma unroll
        for (int o = 16; o > 0; o >>= 1) cc += __shfl_xor_sync(0xffffffffu, cc, o);
        if (lane == 0) red[wid] = cc;
    }
    if (tid < 64) { rowSum[tid] = 0.f; rowSq[tid] = 0.f; vcA[tid] = 0.f; vvA[tid] = 0.f; }

    float    accf[4][8][4];
    uint32_t acch[4][8][2];
#pragma unroll
    for (int mb = 0; mb < 4; ++mb)
#pragma unroll
        for (int q = 0; q < 8; ++q) {
            acch[mb][q][0] = 0u; acch[mb][q][1] = 0u;
#pragma unroll
            for (int c = 0; c < 4; ++c) accf[mb][q][c] = 0.f;
        }

    // ================= GEMM1: 16 chunks, 2-stage ring, f16 acc + promote =========
    for (int c = 0; c < 16; ++c) {
        if (c < 15) {
            const int kb = (c + 1) * KC;
            const uint32_t ab = sb + SM_STAGE + (uint32_t)((c + 1) & 1) * STAGE_BUF;
            const uint32_t bb = ab + A_BYTES;
#pragma unroll
            for (int i = 0; i < 2; ++i) {
                const int s = tid + 128 * i, row = s >> 2, seg = s & 3;
                cp16(ab + (uint32_t)(row * STR_B + seg * 16),
                     tA + (size_t)row * TD + kb + seg * 8);
            }
#pragma unroll
            for (int i = 0; i < 8; ++i) {
                const int s = tid + 128 * i, row = s >> 2, seg = s & 3;
                cp16(bb + (uint32_t)(row * STR_B + seg * 16),
                     W1t + (size_t)row * TD + kb + seg * 8);
            }
            cpcommit();
            cpwait1();
        } else {
            cpwait0();
        }
        __syncthreads();
        const uint32_t ab = sb + SM_STAGE + (uint32_t)(c & 1) * STAGE_BUF;
        const uint32_t aA = ab + aOffW;
        const uint32_t bA = ab + A_BYTES + bOffW;

        uint32_t afr[2][4][4];
        uint32_t bfr[2][4];
#pragma unroll
        for (int mb = 0; mb < 4; ++mb) ldsm4(afr[0][mb], aA + (uint32_t)(mb * 16 * STR_B));
        ldsm4(bfr[0], bA);
#pragma unroll
        for (int ks = 0; ks < 2; ++ks)
#pragma unroll
            for (int q4 = 0; q4 < 4; ++q4) {
                const int s = ks * 4 + q4;
                if (ks == 0)
                    ldsm4(afr[1][q4], aA + (uint32_t)(q4 * 16 * STR_B + 32));
                if (s < 7) {
                    const int ns = s + 1, nks = ns >> 2, nq = ns & 3;
                    ldsm4(bfr[ns & 1], bA + (uint32_t)(nq * 16 * STR_B + nks * 32));
                }
                const uint32_t* bq = bfr[s & 1];
#pragma unroll
                for (int mb = 0; mb < 4; ++mb) {
                    mma16h(acch[mb][2 * q4],     afr[ks][mb], bq[0], bq[1]);
                    mma16h(acch[mb][2 * q4 + 1], afr[ks][mb], bq[2], bq[3]);
                }
            }
        if (c & 1) promote(acch, accf);   // fp32 promotion every K=64
        __syncthreads();
    }

    // ---- issue GEMM2 chunk 0 (overlaps LN/GELU below) ----
    {
        const uint32_t bb = sb + SM_STAGE + A_BYTES;
#pragma unroll
        for (int i = 0; i < 8; ++i) {
            const int s = tid + 128 * i, row = s >> 2, seg = s & 3;
            const uint32_t dst = bb + (uint32_t)(row * STR_B + seg * 16);
            if (row < VD) cp16(dst, W2t + (size_t)row * HD + seg * 8);
            else          stz4(dst);
        }
        cpcommit();
    }

    // ================= LayerNorm stats =================
    {
        float sums[8], sqs[8];
#pragma unroll
        for (int k = 0; k < 8; ++k) { sums[k] = 0.f; sqs[k] = 0.f; }
#pragma unroll
        for (int mb = 0; mb < 4; ++mb)
#pragma unroll
            for (int q = 0; q < 8; ++q)
#pragma unroll
                for (int c = 0; c < 4; ++c) {
                    const int n = n0w + q * 8 + 2 * (lane & 3) + (c & 1);
                    const float x = accf[mb][q][c] + b1s[n];
                    accf[mb][q][c] = x;
                    const int key = (mb << 1) | (c >> 1);
                    sums[key] += x;
                    sqs[key]  = fmaf(x, x, sqs[key]);
                }
#pragma unroll
        for (int o = 1; o <= 2; o <<= 1)
#pragma unroll
            for (int k = 0; k < 8; ++k) {
                sums[k] += __shfl_xor_sync(0xffffffffu, sums[k], o);
                sqs[k]  += __shfl_xor_sync(0xffffffffu, sqs[k], o);
            }
        if ((lane & 3) == 0) {
#pragma unroll
            for (int k = 0; k < 8; ++k) {
                const int r = (k >> 1) * 16 + (k & 1) * 8 + (lane >> 2);
                atomicAdd(&rowSum[r], sums[k]);
                atomicAdd(&rowSq[r],  sqs[k]);
            }
        }
    }
    __syncthreads();

    // ================= normalize + exact GELU + store h (fp16) =================
#pragma unroll
    for (int mb = 0; mb < 4; ++mb)
#pragma unroll
        for (int cp = 0; cp < 2; ++cp) {
            const int r = mb * 16 + cp * 8 + (lane >> 2);
            const float mu   = rowSum[r] * (1.0f / HD);
            const float var  = rowSq[r] * (1.0f / HD) - mu * mu;
            const float rstd = rsqrtf(var + 1e-5f);
#pragma unroll
            for (int q = 0; q < 8; ++q) {
                const int n = n0w + q * 8 + 2 * (lane & 3);
                float y0 = (accf[mb][q][cp * 2]     - mu) * rstd * gms[n]     + bts[n];
                float y1 = (accf[mb][q][cp * 2 + 1] - mu) * rstd * gms[n + 1] + bts[n + 1];
                y0 = 0.5f * y0 * (1.0f + erff(y0 * 0.70710678118654752440f));
                y1 = 0.5f * y1 * (1.0f + erff(y1 * 0.70710678118654752440f));
                sth2(sb + SM_H + (uint32_t)(r * HSTR_B + n * 2), __floats2half2_rn(y0, y1));
            }
        }

    // zero fp32 master for GEMM2 (f16 accs already zero from last promote)
#pragma unroll
    for (int mb = 0; mb < 4; ++mb)
#pragma unroll
        for (int q = 0; q < 8; ++q)
#pragma unroll
            for (int c = 0; c < 4; ++c) accf[mb][q][c] = 0.f;

    // ================= GEMM2 (16 chunks = 2 halves x 8) + cosine ==========
    float vc4[8], vv4[8];
#pragma unroll
    for (int k = 0; k < 8; ++k) { vc4[k] = 0.f; vv4[k] = 0.f; }

    for (int gc = 0; gc < 16; ++gc) {
        const int kc8 = gc & 7;
        if (gc == 8) {
            // fold half 0 (accf holds promoted v partials)
#pragma unroll
            for (int mb = 0; mb < 4; ++mb)
#pragma unroll
                for (int q = 0; q < 8; ++q)
#pragma unroll
                    for (int c = 0; c < 4; ++c) {
                        const int n = n0w + q * 8 + 2 * (lane & 3) + (c & 1);
                        const float v = accf[mb][q][c] + b2s[n];
                        const int key = (mb << 1) | (c >> 1);
                        vc4[key] = fmaf(v, cts[n], vc4[key]);
                        vv4[key] = fmaf(v, v,     vv4[key]);
                        accf[mb][q][c] = 0.f;
                    }
        }
        if (gc < 15) {
            const int nh = (gc + 1) >> 3, nk = (gc + 1) & 7;
            const uint32_t bb = sb + SM_STAGE + (uint32_t)((gc + 1) & 1) * STAGE_BUF + A_BYTES;
            const int kb = nk * KC;
#pragma unroll
            for (int i = 0; i < 8; ++i) {
                const int s = tid + 128 * i, row = s >> 2, seg = s & 3;
                const int n = nh * 256 + row;
                const uint32_t dst = bb + (uint32_t)(row * STR_B + seg * 16);
                if (n < VD) cp16(dst, W2t + (size_t)n * HD + kb + seg * 8);
                else        stz4(dst);
            }
            cpcommit();
            cpwait1();
        } else {
            cpwait0();
        }
        __syncthreads();
        const uint32_t aA = sb + SM_H + hOffW + (uint32_t)(kc8 * KC * 2);
        const uint32_t bA = sb + SM_STAGE + (uint32_t)(gc & 1) * STAGE_BUF + A_BYTES + bOffW;

        uint32_t afr[2][4][4];
        uint32_t bfr[2][4];
#pragma unroll
        for (int mb = 0; mb < 4; ++mb) ldsm4(afr[0][mb], aA + (uint32_t)(mb * 16 * HSTR_B));
        ldsm4(bfr[0], bA);
#pragma unroll
        for (int ks = 0; ks < 2; ++ks)
#pragma unroll
            for (int q4 = 0; q4 < 4; ++q4) {
                const int s = ks * 4 + q4;
                if (ks == 0)
                    ldsm4(afr[1][q4], aA + (uint32_t)(q4 * 16 * HSTR_B + 32));
                if (s < 7) {
                    const int ns = s + 1, nks = ns >> 2, nq = ns & 3;
                    ldsm4(bfr[ns & 1], bA + (uint32_t)(nq * 16 * STR_B + nks * 32));
                }
                const uint32_t* bq = bfr[s & 1];
#pragma unroll
                for (int mb = 0; mb < 4; ++mb) {
                    mma16h(acch[mb][2 * q4],     afr[ks][mb], bq[0], bq[1]);
                    mma16h(acch[mb][2 * q4 + 1], afr[ks][mb], bq[2], bq[3]);
                }
            }
        if (gc & 1) promote(acch, accf);
        __syncthreads();
    }
    // fold half 1
#pragma unroll
    for (int mb = 0; mb < 4; ++mb)
#pragma unroll
        for (int q = 0; q < 8; ++q)
#pragma unroll
            for (int c = 0; c < 4; ++c) {
                const int n = 256 + n0w + q * 8 + 2 * (lane & 3) + (c & 1);
                const float v = accf[mb][q][c] + b2s[n];
                const int key = (mb << 1) | (c >> 1);
                vc4[key] = fmaf(v, cts[n], vc4[key]);
                vv4[key] = fmaf(v, v,     vv4[key]);
            }

#pragma unroll
    for (int o = 1; o <= 2; o <<= 1)
#pragma unroll
        for (int k = 0; k < 8; ++k) {
            vc4[k] += __shfl_xor_sync(0xffffffffu, vc4[k], o);
            vv4[k] += __shfl_xor_sync(0xffffffffu, vv4[k], o);
        }
    if ((lane & 3) == 0) {
#pragma unroll
        for (int k = 0; k < 8; ++k) {
            const int r = (k >> 1) * 16 + (k & 1) * 8 + (lane >> 2);
            atomicAdd(&vcA[r], vc4[k]);
            atomicAdd(&vvA[r], vv4[k]);
        }
    }
    __syncthreads();

    float dist = 0.f;
    if (tid < 64) {
        float cn2 = red[0] + red[1] + red[2] + red[3];
        const float cn = fmaxf(sqrtf(cn2), 1e-8f);
        const float vn = fmaxf(sqrtf(vvA[tid]), 1e-8f);
        dist = 1.0f - vcA[tid] / (vn * cn);
    }
#pragma unroll
    for (int o = 16; o > 0; o >>= 1) dist += __shfl_xor_sync(0xffffffffu, dist, o);
    if (tid < 64 && lane == 0) red[4 + wid] = dist;
    __syncthreads();
    if (tid == 0) {
        if (task < out_size)
            atomicAdd(&out[task], red[4] + red[5]);
        __threadfence();
        const unsigned int old = atomicAdd(&g_count, 1u);
        *flag = (old == (unsigned)(NTASK * (NB / MT) - 1)) ? 1 : 0;
    }
    __syncthreads();

    // ---- last CTA finalizes: scale + argmin ----
    if (*flag) {
        __threadfence();
        float v = 0.0f;
        if (tid < NTASK && tid < out_size) {
            v = out[tid] * (1.0f / (float)NB);
            out[tid] = v;
        }
        if (tid < NTASK) b1s[tid] = v;
        __syncthreads();
        if (tid == 0) {
            int best = 0;
            float bv = b1s[0];
#pragma unroll 1
            for (int i = 1; i < NTASK; ++i)
                if (b1s[i] < bv) { bv = b1s[i]; best = i; }
            if (out_size > 64) out[64] = (float)best;
            g_count = 0u;
        }
    }
}

extern "C" void kernel_launch(void* const* d_in, const int* in_sizes, int n_in,
                              void* d_out, int out_size) {
    const float* t_feat = (const float*)d_in[0];
    const float* W1     = (const float*)d_in[1];
    const float* b1     = (const float*)d_in[2];
    const float* gamma  = (const float*)d_in[3];
    const float* beta   = (const float*)d_in[4];
    const float* W2     = (const float*)d_in[5];
    const float* b2     = (const float*)d_in[6];
    const float* cent   = (const float*)d_in[7];
    float* out = (float*)d_out;

    cudaFuncSetAttribute(router_h16_kernel,
                         cudaFuncAttributeMaxDynamicSharedMemorySize, SMEM_TOTAL);

    convert_kernel<<<2048, 256>>>(t_feat, W1, W2, out, out_size);
    dim3 grid(NB / MT, NTASK);
    router_h16_kernel<<<grid, THREADS, SMEM_TOTAL>>>(
        b1, gamma, beta, b2, cent, out, out_size);
}